// round 4
// baseline (speedup 1.0000x reference)
#include <cuda_runtime.h>

#define BB 8
#define NN 2048
#define FIN 128
#define ODIM 256
#define NROWS (BB*NN)

// scratch (static device arrays — no allocation)
__device__ __align__(16) float g_T[NROWS * ODIM];   // X @ W^T  (16 MB)
__device__ __align__(16) float g_src[NROWS * 12];   // per row: -src[4], exp(src)[4], exp(0.2src)[4]
__device__ __align__(16) float g_dst[NROWS * 4];    // per row: dst[4]

// ---------------------------------------------------------------------------
// Kernel 1: T = X @ W^T   (M=16384, N=256, K=128)
// f32x2 FMA with pairs along K: acc.lo accumulates even k, acc.hi odd k.
// Tile 128(m) x 64(c), 256 threads, thread tile 8x4, k-step 2.
// Strides 130: conflict-free LDS.64 for both A (row-broadcast) and B operands.
// ---------------------------------------------------------------------------
#define XS 130
#define WSS 130
#define GEMM_SMEM ((128*XS + 64*WSS) * 4)   // 99,840 B -> 2 blocks/SM

__global__ __launch_bounds__(256, 2) void gemm_kernel(const float* __restrict__ X,
                                                      const float* __restrict__ W) {
    extern __shared__ float sm[];
    float* Xs = sm;              // [128][XS]
    float* Ws = sm + 128 * XS;   // [64][WSS]  (col-major over outputs: row c holds k=0..127)
    const int tid = threadIdx.x;
    const int m0 = blockIdx.y * 128;
    const int c0 = blockIdx.x * 64;

    // fill Xs (float4 global loads, scalar smem stores due to stride 130)
#pragma unroll
    for (int it = 0; it < 16; it++) {
        int g = tid + it * 256;          // 0..4095
        int r = g >> 5, kq = g & 31;
        float4 v = ((const float4*)(X + (size_t)(m0 + r) * FIN))[kq];
        float* dst = &Xs[r * XS + kq * 4];
        dst[0] = v.x; dst[1] = v.y; dst[2] = v.z; dst[3] = v.w;
    }
    // fill Ws: W[c0+c][k] -> Ws[c][k]
#pragma unroll
    for (int it = 0; it < 8; it++) {
        int g = tid + it * 256;          // 0..2047
        int c = g >> 5, kq = g & 31;
        float4 v = ((const float4*)(W + (size_t)(c0 + c) * FIN))[kq];
        float* dst = &Ws[c * WSS + kq * 4];
        dst[0] = v.x; dst[1] = v.y; dst[2] = v.z; dst[3] = v.w;
    }
    __syncthreads();

    const int tx = tid & 15, ty = tid >> 4;
    const int r0 = ty * 8;               // 8 rows per thread
    // cols: c = tx + 16*j, j<4

    unsigned long long acc[8][4];
#pragma unroll
    for (int i = 0; i < 8; i++)
#pragma unroll
        for (int j = 0; j < 4; j++) acc[i][j] = 0ull;

#pragma unroll 4
    for (int k0 = 0; k0 < 128; k0 += 2) {
        unsigned long long bv[4], av[8];
#pragma unroll
        for (int j = 0; j < 4; j++)
            bv[j] = *(const unsigned long long*)&Ws[(tx + 16 * j) * WSS + k0];
#pragma unroll
        for (int i = 0; i < 8; i++)
            av[i] = *(const unsigned long long*)&Xs[(r0 + i) * XS + k0];
#pragma unroll
        for (int i = 0; i < 8; i++)
#pragma unroll
            for (int j = 0; j < 4; j++)
                asm("fma.rn.f32x2 %0, %1, %2, %0;"
                    : "+l"(acc[i][j]) : "l"(av[i]), "l"(bv[j]));
    }

    // epilogue: T[r][c] = acc.lo + acc.hi
#pragma unroll
    for (int i = 0; i < 8; i++) {
        float* Tr = g_T + (size_t)(m0 + r0 + i) * ODIM + c0;
#pragma unroll
        for (int j = 0; j < 4; j++) {
            float lo = __uint_as_float((unsigned)(acc[i][j] & 0xffffffffull));
            float hi = __uint_as_float((unsigned)(acc[i][j] >> 32));
            Tr[tx + 16 * j] = lo + hi;
        }
    }
}

// ---------------------------------------------------------------------------
// Kernel 2: per-row src/dst projections + exps. One warp per row.
// ---------------------------------------------------------------------------
__global__ __launch_bounds__(256) void prep_kernel(const float* __restrict__ asrc,
                                                   const float* __restrict__ adst) {
    __shared__ float sa[256], sd[256];
    const int tid = threadIdx.x;
    sa[tid] = asrc[tid];
    sd[tid] = adst[tid];
    __syncthreads();

    const int l = tid & 31, w = tid >> 5;
    const int row = blockIdx.x * 8 + w;

    float s[4] = {0.f, 0.f, 0.f, 0.f}, d[4] = {0.f, 0.f, 0.f, 0.f};
    const float* Tr = g_T + (size_t)row * ODIM;
#pragma unroll
    for (int k = 0; k < 8; k++) {
        int e = k * 32 + l;          // element index 0..255; head = e/64 = k>>1
        float v = Tr[e];
        s[k >> 1] += v * sa[e];
        d[k >> 1] += v * sd[e];
    }
#pragma unroll
    for (int off = 16; off; off >>= 1) {
#pragma unroll
        for (int h = 0; h < 4; h++) {
            s[h] += __shfl_xor_sync(0xffffffffu, s[h], off);
            d[h] += __shfl_xor_sync(0xffffffffu, d[h], off);
        }
    }
    if (l == 0) {
#pragma unroll
        for (int h = 0; h < 4; h++) {
            g_src[row * 12 + h]     = -s[h];
            g_src[row * 12 + 4 + h] = expf(s[h]);
            g_src[row * 12 + 8 + h] = expf(0.2f * s[h]);
            g_dst[row * 4 + h]      = d[h];
        }
    }
}

// ---------------------------------------------------------------------------
// Kernel 3: masked softmax-diagonal scan over A + fused output scaling.
// Block = 256 thr (8 warps), each warp owns 4 rows; lanes stream j.
// A loads software-pipelined to depth 4 (16 outstanding LDG/warp).
// ---------------------------------------------------------------------------
#define SCAN_SMEM (3 * NN * 4 * 4)

#define ACC1(AP, AN, A_, D_, NS_, P_, Q_)                                   \
    asm("{ .reg .pred p;\n\t"                                               \
        "setp.ge.f32 p, %3, %4;\n\t"                                        \
        "@p  fma.rn.f32 %0, %2, %5, %0;\n\t"                                \
        "@!p fma.rn.f32 %1, %2, %6, %1; }"                                  \
        : "+f"(AP), "+f"(AN)                                                \
        : "f"(A_), "f"(D_), "f"(NS_), "f"(P_), "f"(Q_))

__global__ __launch_bounds__(256, 2) void scan_kernel(const float* __restrict__ A,
                                                      float* __restrict__ out) {
    extern __shared__ float sm[];
    float4* sdst = (float4*)sm;               // [NN] dst per head
    float4* spd  = (float4*)(sm + NN * 4);    // exp(dst)
    float4* sqd  = (float4*)(sm + NN * 8);    // exp(0.2 dst)
    const int tid = threadIdx.x;
    const int b = blockIdx.y;
    const int l = tid & 31;
    const int r0 = blockIdx.x * 32 + (tid >> 5) * 4;   // row base within batch

    // prologue: load dst table for this batch, compute exps into smem
    {
        const float4* gd = (const float4*)(g_dst + (size_t)b * NN * 4);
        for (int t = tid; t < NN; t += 256) {
            float4 dv = gd[t];
            sdst[t] = dv;
            spd[t] = make_float4(__expf(dv.x), __expf(dv.y), __expf(dv.z), __expf(dv.w));
            sqd[t] = make_float4(__expf(0.2f * dv.x), __expf(0.2f * dv.y),
                                 __expf(0.2f * dv.z), __expf(0.2f * dv.w));
        }
    }
    __syncthreads();

    float ns[4][4];
#pragma unroll
    for (int ii = 0; ii < 4; ii++)
#pragma unroll
        for (int h = 0; h < 4; h++)
            ns[ii][h] = g_src[(size_t)(b * NN + r0 + ii) * 12 + h];

    const float* Ar[4];
#pragma unroll
    for (int ii = 0; ii < 4; ii++)
        Ar[ii] = A + ((size_t)b * NN + (r0 + ii)) * NN;

    float ap[4][4], an[4][4];
#pragma unroll
    for (int ii = 0; ii < 4; ii++)
#pragma unroll
        for (int h = 0; h < 4; h++) { ap[ii][h] = 0.f; an[ii][h] = 0.f; }

    // depth-4 pipelined scan: stage s covers j = jt4*128 + s*32 + l
    float abuf[4][4];                    // [stage][row]
#pragma unroll
    for (int s = 0; s < 4; s++)
#pragma unroll
        for (int ii = 0; ii < 4; ii++)
            abuf[s][ii] = Ar[ii][l + 32 * s];

    for (int jt4 = 0; jt4 < 16; jt4++) {
#pragma unroll
        for (int s = 0; s < 4; s++) {
            const int j = jt4 * 128 + s * 32 + l;
            // prefetch next round; on the last round clamp to current j (L1 hit)
            const int jn = (jt4 < 15) ? j + 128 : j;
            float4 dv = sdst[j];
            float4 pv = spd[j];
            float4 qv = sqd[j];
            float anx[4];
#pragma unroll
            for (int ii = 0; ii < 4; ii++) anx[ii] = Ar[ii][jn];
#pragma unroll
            for (int ii = 0; ii < 4; ii++) {
                float a = abuf[s][ii];
                ACC1(ap[ii][0], an[ii][0], a, dv.x, ns[ii][0], pv.x, qv.x);
                ACC1(ap[ii][1], an[ii][1], a, dv.y, ns[ii][1], pv.y, qv.y);
                ACC1(ap[ii][2], an[ii][2], a, dv.z, ns[ii][2], pv.z, qv.z);
                ACC1(ap[ii][3], an[ii][3], a, dv.w, ns[ii][3], pv.w, qv.w);
            }
#pragma unroll
            for (int ii = 0; ii < 4; ii++) abuf[s][ii] = anx[ii];
        }
    }

    // warp reduction (all lanes end with full sums)
#pragma unroll
    for (int off = 16; off; off >>= 1)
#pragma unroll
        for (int ii = 0; ii < 4; ii++)
#pragma unroll
            for (int h = 0; h < 4; h++) {
                ap[ii][h] += __shfl_xor_sync(0xffffffffu, ap[ii][h], off);
                an[ii][h] += __shfl_xor_sync(0xffffffffu, an[ii][h], off);
            }

    const float* sdstf = sm;
    const float* spdf  = sm + NN * 4;
    const float* sqdf  = sm + NN * 8;

#pragma unroll
    for (int ii = 0; ii < 4; ii++) {
        const int il = r0 + ii;
        const size_t grow = (size_t)b * NN + il;
        float diag[4];
#pragma unroll
        for (int h = 0; h < 4; h++) {
            float ps = g_src[grow * 12 + 4 + h];
            float qs = g_src[grow * 12 + 8 + h];
            float denom = ps * ap[ii][h] + qs * an[ii][h];
            float dsth = sdstf[il * 4 + h];
            float num = (dsth >= ns[ii][h]) ? ps * spdf[il * 4 + h]
                                            : qs * sqdf[il * 4 + h];
            diag[h] = num / denom;
        }
        const float4* Tr = (const float4*)(g_T + grow * ODIM);
        float4* Or = (float4*)(out + grow * ODIM);
        float4 t0 = Tr[l];        // floats 4l..4l+3      -> head l>>4
        float4 t1 = Tr[32 + l];   // floats 128+4l..      -> head 2+(l>>4)
        float d0 = diag[l >> 4], d1 = diag[2 + (l >> 4)];
        Or[l]      = make_float4(t0.x * d0, t0.y * d0, t0.z * d0, t0.w * d0);
        Or[32 + l] = make_float4(t1.x * d1, t1.y * d1, t1.z * d1, t1.w * d1);
    }
}

// ---------------------------------------------------------------------------
extern "C" void kernel_launch(void* const* d_in, const int* in_sizes, int n_in,
                              void* d_out, int out_size) {
    const float* A    = (const float*)d_in[0];
    const float* X    = (const float*)d_in[1];
    const float* W    = (const float*)d_in[2];
    const float* asrc = (const float*)d_in[3];
    const float* adst = (const float*)d_in[4];
    float* out = (float*)d_out;

    cudaFuncSetAttribute(gemm_kernel, cudaFuncAttributeMaxDynamicSharedMemorySize, GEMM_SMEM);
    cudaFuncSetAttribute(scan_kernel, cudaFuncAttributeMaxDynamicSharedMemorySize, SCAN_SMEM);

    gemm_kernel<<<dim3(ODIM / 64, 128), 256, GEMM_SMEM>>>(X, W);
    prep_kernel<<<NROWS / 8, 256>>>(asrc, adst);
    scan_kernel<<<dim3(NN / 32, BB), 256, SCAN_SMEM>>>(A, out);
}

// round 7
// speedup vs baseline: 1.2357x; 1.2357x over previous
#include <cuda_runtime.h>

#define BB 8
#define NN 2048
#define FIN 128
#define ODIM 256
#define NROWS (BB*NN)

// scratch (static device arrays — no allocation)
__device__ __align__(16) float g_T[NROWS * ODIM];   // X @ W^T (16 MB)
__device__ __align__(16) float g_r[NROWS * 4];      // exp(-0.8*src) per head
__device__ __align__(16) float g_ed[NROWS * 8];     // exp(dst)[4], exp(0.2*dst)[4]

// ---------------------------------------------------------------------------
// Kernel 1: T = X @ W^T  (M=16384, N=256, K=128)
// f32x2 pairs along K (acc.lo = even k, acc.hi = odd k), k-step 4.
// Tile 128(m) x 64(c), 256 threads, thread tile 8 rows x 4 cols.
// Per k-quad: 8 A LDS.128 + 4 B LDS.128 -> 64 FMA2. Smem 101KB -> 2 blocks/SM.
// ---------------------------------------------------------------------------
#define XS 132
#define WCS 132
#define GEMM_SMEM ((128*XS + 64*WCS) * 4)   // 101,376 B

__global__ __launch_bounds__(256, 2) void gemm_kernel(const float* __restrict__ X,
                                                      const float* __restrict__ W) {
    extern __shared__ float sm[];
    float* Xs = sm;               // [m][k], stride XS
    float* Ws = sm + 128 * XS;    // [c][k], stride WCS
    const int tid = threadIdx.x;
    const int m0 = blockIdx.y * 128;
    const int c0 = blockIdx.x * 64;

    // load X tile: float4 global -> float4 smem (both coalesced/conflict-free)
#pragma unroll
    for (int it = 0; it < 16; it++) {
        int g = tid + it * 256;          // 0..4095
        int r = g >> 5, kq = g & 31;
        float4 v = ((const float4*)(X + (size_t)(m0 + r) * FIN))[kq];
        *(float4*)&Xs[r * XS + 4 * kq] = v;
    }
    // load W tile: W[c0+c][k] -> Ws[c][k]
#pragma unroll
    for (int it = 0; it < 8; it++) {
        int g = tid + it * 256;          // 0..2047
        int c = g >> 5, kq = g & 31;
        float4 v = ((const float4*)(W + (size_t)(c0 + c) * FIN))[kq];
        *(float4*)&Ws[c * WCS + 4 * kq] = v;
    }
    __syncthreads();

    const int tx = tid & 15, ty = tid >> 4;
    const int r0 = ty * 8;               // 8 rows per thread; cols tx+16j

    unsigned long long acc[8][4];
#pragma unroll
    for (int i = 0; i < 8; i++)
#pragma unroll
        for (int j = 0; j < 4; j++) acc[i][j] = 0ull;

#pragma unroll 2
    for (int k0 = 0; k0 < 128; k0 += 4) {
        ulonglong2 bv[4];
#pragma unroll
        for (int j = 0; j < 4; j++)
            bv[j] = *(const ulonglong2*)&Ws[(tx + 16 * j) * WCS + k0];
#pragma unroll
        for (int i = 0; i < 8; i++) {
            ulonglong2 av = *(const ulonglong2*)&Xs[(r0 + i) * XS + k0];
#pragma unroll
            for (int j = 0; j < 4; j++) {
                asm("fma.rn.f32x2 %0, %1, %2, %0;"
                    : "+l"(acc[i][j]) : "l"(av.x), "l"(bv[j].x));
                asm("fma.rn.f32x2 %0, %1, %2, %0;"
                    : "+l"(acc[i][j]) : "l"(av.y), "l"(bv[j].y));
            }
        }
    }

    // epilogue: T[r][c] = acc.lo + acc.hi
#pragma unroll
    for (int i = 0; i < 8; i++) {
        float* Tr = g_T + (size_t)(m0 + r0 + i) * ODIM + c0;
#pragma unroll
        for (int j = 0; j < 4; j++) {
            float lo, hi;
            asm("mov.b64 {%0, %1}, %2;" : "=f"(lo), "=f"(hi) : "l"(acc[i][j]));
            Tr[tx + 16 * j] = lo + hi;
        }
    }
}

// ---------------------------------------------------------------------------
// Kernel 2: per-row src/dst projections + exp tables. One warp per row.
// ---------------------------------------------------------------------------
__global__ __launch_bounds__(256) void prep_kernel(const float* __restrict__ asrc,
                                                   const float* __restrict__ adst) {
    __shared__ float sa[256], sd[256];
    const int tid = threadIdx.x;
    sa[tid] = asrc[tid];
    sd[tid] = adst[tid];
    __syncthreads();

    const int l = tid & 31, w = tid >> 5;
    const int row = blockIdx.x * 8 + w;

    float s[4] = {0.f, 0.f, 0.f, 0.f}, d[4] = {0.f, 0.f, 0.f, 0.f};
    const float* Tr = g_T + (size_t)row * ODIM;
#pragma unroll
    for (int k = 0; k < 8; k++) {
        int e = k * 32 + l;          // element 0..255; head = k>>1
        float v = Tr[e];
        s[k >> 1] += v * sa[e];
        d[k >> 1] += v * sd[e];
    }
#pragma unroll
    for (int off = 16; off; off >>= 1) {
#pragma unroll
        for (int h = 0; h < 4; h++) {
            s[h] += __shfl_xor_sync(0xffffffffu, s[h], off);
            d[h] += __shfl_xor_sync(0xffffffffu, d[h], off);
        }
    }
    if (l == 0) {
#pragma unroll
        for (int h = 0; h < 4; h++) {
            g_r[row * 4 + h]      = expf(-0.8f * s[h]);
            g_ed[row * 8 + h]     = expf(d[h]);
            g_ed[row * 8 + 4 + h] = expf(0.2f * d[h]);
        }
    }
}

// ---------------------------------------------------------------------------
// Kernel 3: masked softmax-diagonal scan via the max identity:
//   acc_ih = sum_j A_ij * max(ed_jh, r_ih * eq_jh)
//   diag_ih = max(ed_ih, r_ih * eq_ih) / acc_ih
// Block = 256 thr (8 warps), warp owns 4 rows; lanes stream j (stride 32).
// A loads front-batched one full 128-j round ahead (16 LDG in flight/warp).
// ---------------------------------------------------------------------------
#define SCAN_SMEM (NN * 8 * 4)   // 64 KB -> 2+ blocks/SM

__global__ __launch_bounds__(256, 2) void scan_kernel(const float* __restrict__ A,
                                                      float* __restrict__ out) {
    extern __shared__ float sm[];
    float4* sed = (float4*)sm;             // exp(dst) per head, [NN]
    float4* seq = (float4*)(sm + NN * 4);  // exp(0.2*dst) per head, [NN]
    const int tid = threadIdx.x;
    const int b = blockIdx.y;
    const int l = tid & 31;
    const int r0 = blockIdx.x * 32 + (tid >> 5) * 4;

    // prologue: copy tables for this batch into smem
    {
        const float4* ge = (const float4*)(g_ed + (size_t)b * NN * 8);
        for (int t = tid; t < NN; t += 256) {
            sed[t] = ge[2 * t];
            seq[t] = ge[2 * t + 1];
        }
    }
    __syncthreads();

    float rr[4][4];
#pragma unroll
    for (int ii = 0; ii < 4; ii++) {
        float4 rv = *(const float4*)&g_r[(size_t)(b * NN + r0 + ii) * 4];
        rr[ii][0] = rv.x; rr[ii][1] = rv.y; rr[ii][2] = rv.z; rr[ii][3] = rv.w;
    }

    const float* Ar[4];
#pragma unroll
    for (int ii = 0; ii < 4; ii++)
        Ar[ii] = A + ((size_t)b * NN + (r0 + ii)) * NN;

    float acc[4][4];
#pragma unroll
    for (int ii = 0; ii < 4; ii++)
#pragma unroll
        for (int h = 0; h < 4; h++) acc[ii][h] = 0.f;

    // round = 128 js (4 stages of 32); cur holds this round's A, nxt prefetched
    float cur[4][4], nxt[4][4];            // [stage][row]
#pragma unroll
    for (int s = 0; s < 4; s++)
#pragma unroll
        for (int ii = 0; ii < 4; ii++)
            cur[s][ii] = __ldcs(&Ar[ii][l + 32 * s]);

    for (int rnd = 0; rnd < 16; rnd++) {
        // front-batched prefetch of the entire next round (16 LDG, MLP=16)
        const int jb = (rnd < 15) ? (rnd + 1) * 128 + l : rnd * 128 + l;
#pragma unroll
        for (int s = 0; s < 4; s++)
#pragma unroll
            for (int ii = 0; ii < 4; ii++)
                nxt[s][ii] = __ldcs(&Ar[ii][jb + 32 * s]);

#pragma unroll
        for (int s = 0; s < 4; s++) {
            const int j = rnd * 128 + s * 32 + l;
            float4 ed = sed[j];
            float4 eq = seq[j];
#pragma unroll
            for (int ii = 0; ii < 4; ii++) {
                const float a = cur[s][ii];
                acc[ii][0] = fmaf(a, fmaxf(ed.x, rr[ii][0] * eq.x), acc[ii][0]);
                acc[ii][1] = fmaf(a, fmaxf(ed.y, rr[ii][1] * eq.y), acc[ii][1]);
                acc[ii][2] = fmaf(a, fmaxf(ed.z, rr[ii][2] * eq.z), acc[ii][2]);
                acc[ii][3] = fmaf(a, fmaxf(ed.w, rr[ii][3] * eq.w), acc[ii][3]);
            }
        }
#pragma unroll
        for (int s = 0; s < 4; s++)
#pragma unroll
            for (int ii = 0; ii < 4; ii++) cur[s][ii] = nxt[s][ii];
    }

    // warp reduction (all lanes end with full sums)
#pragma unroll
    for (int off = 16; off; off >>= 1)
#pragma unroll
        for (int ii = 0; ii < 4; ii++)
#pragma unroll
            for (int h = 0; h < 4; h++)
                acc[ii][h] += __shfl_xor_sync(0xffffffffu, acc[ii][h], off);

    const float* sedf = sm;
    const float* seqf = sm + NN * 4;

#pragma unroll
    for (int ii = 0; ii < 4; ii++) {
        const int il = r0 + ii;
        const size_t grow = (size_t)b * NN + il;
        float diag[4];
#pragma unroll
        for (int h = 0; h < 4; h++) {
            float num = fmaxf(sedf[il * 4 + h], rr[ii][h] * seqf[il * 4 + h]);
            diag[h] = num / acc[ii][h];
        }
        const float4* Tr = (const float4*)(g_T + grow * ODIM);
        float4* Or = (float4*)(out + grow * ODIM);
        float4 t0 = Tr[l];        // floats 4l..4l+3   -> head l>>4
        float4 t1 = Tr[32 + l];   // floats 128+4l..   -> head 2+(l>>4)
        float d0 = diag[l >> 4], d1 = diag[2 + (l >> 4)];
        Or[l]      = make_float4(t0.x * d0, t0.y * d0, t0.z * d0, t0.w * d0);
        Or[32 + l] = make_float4(t1.x * d1, t1.y * d1, t1.z * d1, t1.w * d1);
    }
}

// ---------------------------------------------------------------------------
extern "C" void kernel_launch(void* const* d_in, const int* in_sizes, int n_in,
                              void* d_out, int out_size) {
    const float* A    = (const float*)d_in[0];
    const float* X    = (const float*)d_in[1];
    const float* W    = (const float*)d_in[2];
    const float* asrc = (const float*)d_in[3];
    const float* adst = (const float*)d_in[4];
    float* out = (float*)d_out;

    cudaFuncSetAttribute(gemm_kernel, cudaFuncAttributeMaxDynamicSharedMemorySize, GEMM_SMEM);
    cudaFuncSetAttribute(scan_kernel, cudaFuncAttributeMaxDynamicSharedMemorySize, SCAN_SMEM);

    gemm_kernel<<<dim3(ODIM / 64, NROWS / 128), 256, GEMM_SMEM>>>(X, W);
    prep_kernel<<<NROWS / 8, 256>>>(asrc, adst);
    scan_kernel<<<dim3(NN / 32, BB), 256, SCAN_SMEM>>>(A, out);
}

// round 9
// speedup vs baseline: 1.2428x; 1.0058x over previous
#include <cuda_runtime.h>

#define BB 8
#define NN 2048
#define FIN 128
#define ODIM 256
#define NROWS (BB*NN)

// scratch (static device arrays — no allocation)
__device__ __align__(16) float g_T[NROWS * ODIM];   // X @ W^T (16 MB)
__device__ __align__(16) float g_w[8 * FIN];        // wsrc[4][128], wdst[4][128]
__device__ __align__(16) float g_r[NROWS * 4];      // exp(-0.8*src) per head
__device__ __align__(16) float g_ed[NROWS * 8];     // exp(dst)[4], exp(0.2*dst)[4]
__device__ __align__(16) float g_num[NROWS * 4];    // max(ed, r*eq) per row/head
__device__ __align__(16) float g_acc[NROWS * 4];    // scan denominators

// ---------------------------------------------------------------------------
// Kernel 1: head-projection vectors  w[s][h][k] = sum_d a[h][d] * W[h*64+d][k]
// grid 8 (= s*4+h ... actually h*2+s), block 256 (2 d-halves x 128 k)
// ---------------------------------------------------------------------------
__global__ __launch_bounds__(256) void vec_kernel(const float* __restrict__ W,
                                                  const float* __restrict__ asrc,
                                                  const float* __restrict__ adst) {
    const int h = blockIdx.x >> 1, s = blockIdx.x & 1;
    const float* av = s ? adst : asrc;      // (4,64) flat
    const int tid = threadIdx.x;
    const int g = tid >> 7;                 // d-half
    const int k = tid & 127;
    float acc = 0.f;
#pragma unroll 8
    for (int dd = 0; dd < 32; dd++) {
        int d = g * 32 + dd;
        acc = fmaf(av[h * 64 + d], W[(size_t)(h * 64 + d) * FIN + k], acc);
    }
    __shared__ float red[256];
    red[tid] = acc;
    __syncthreads();
    if (g == 0)
        g_w[(s * 4 + h) * FIN + k] = red[k] + red[128 + k];
}

// ---------------------------------------------------------------------------
// Kernel 2: per-row src/dst from X (one warp per row) + exp tables + numerator
// ---------------------------------------------------------------------------
__global__ __launch_bounds__(256) void row_kernel(const float* __restrict__ X) {
    __shared__ float sw[8 * FIN];
    const int tid = threadIdx.x;
    ((float4*)sw)[tid] = ((const float4*)g_w)[tid];   // 256 float4 = 8*128 floats
    __syncthreads();

    const int l = tid & 31, w = tid >> 5;
    const int row = blockIdx.x * 8 + w;
    float4 x4 = ((const float4*)(X + (size_t)row * FIN))[l];
    float dot[8];
#pragma unroll
    for (int v = 0; v < 8; v++) {
        float4 w4 = ((const float4*)(sw + v * FIN))[l];
        dot[v] = x4.x * w4.x + x4.y * w4.y + x4.z * w4.z + x4.w * w4.w;
    }
#pragma unroll
    for (int off = 16; off; off >>= 1)
#pragma unroll
        for (int v = 0; v < 8; v++)
            dot[v] += __shfl_xor_sync(0xffffffffu, dot[v], off);

    if (l == 0) {
#pragma unroll
        for (int h = 0; h < 4; h++) {
            float src = dot[h], dst = dot[4 + h];
            float r  = expf(-0.8f * src);
            float ed = expf(dst);
            float eq = expf(0.2f * dst);
            g_r[row * 4 + h]      = r;
            g_ed[row * 8 + h]     = ed;
            g_ed[row * 8 + 4 + h] = eq;
            g_num[row * 4 + h]    = fmaxf(ed, r * eq);
        }
    }
}

// ---------------------------------------------------------------------------
// Kernel 3: FUSED heterogeneous kernel. Even blocks: GEMM tile. Odd blocks:
// masked-scan accumulate. Parity interleave puts ~1 of each type per SM per
// wave so scan (mem-bound) fills gemm's (fma-bound) issue gaps.
// ---------------------------------------------------------------------------
#define XS 132
#define WCS 132
#define FUSED_SMEM ((128*XS + 64*WCS) * 4)   // 101,376 B -> 2 blocks/SM

__global__ __launch_bounds__(256, 2) void fused_kernel(const float* __restrict__ A,
                                                       const float* __restrict__ X,
                                                       const float* __restrict__ W) {
    extern __shared__ float sm[];
    const int tid = threadIdx.x;

    if (!(blockIdx.x & 1)) {
        // ================= GEMM block: T = X @ W^T tile 128x64 =================
        float* Xs = sm;               // [m][k], stride XS
        float* Ws = sm + 128 * XS;    // [c][k], stride WCS
        const int gid = blockIdx.x >> 1;
        const int m0 = (gid >> 2) * 128;
        const int c0 = (gid & 3) * 64;

#pragma unroll
        for (int it = 0; it < 16; it++) {
            int g = tid + it * 256;
            int r = g >> 5, kq = g & 31;
            float4 v = ((const float4*)(X + (size_t)(m0 + r) * FIN))[kq];
            *(float4*)&Xs[r * XS + 4 * kq] = v;
        }
#pragma unroll
        for (int it = 0; it < 8; it++) {
            int g = tid + it * 256;
            int c = g >> 5, kq = g & 31;
            float4 v = ((const float4*)(W + (size_t)(c0 + c) * FIN))[kq];
            *(float4*)&Ws[c * WCS + 4 * kq] = v;
        }
        __syncthreads();

        const int tx = tid & 15, ty = tid >> 4;
        const int r0 = ty * 8;

        unsigned long long acc[8][4];
#pragma unroll
        for (int i = 0; i < 8; i++)
#pragma unroll
            for (int j = 0; j < 4; j++) acc[i][j] = 0ull;

#pragma unroll 2
        for (int k0 = 0; k0 < 128; k0 += 4) {
            ulonglong2 bv[4];
#pragma unroll
            for (int j = 0; j < 4; j++)
                bv[j] = *(const ulonglong2*)&Ws[(tx + 16 * j) * WCS + k0];
#pragma unroll
            for (int i = 0; i < 8; i++) {
                ulonglong2 av = *(const ulonglong2*)&Xs[(r0 + i) * XS + k0];
#pragma unroll
                for (int j = 0; j < 4; j++) {
                    asm("fma.rn.f32x2 %0, %1, %2, %0;"
                        : "+l"(acc[i][j]) : "l"(av.x), "l"(bv[j].x));
                    asm("fma.rn.f32x2 %0, %1, %2, %0;"
                        : "+l"(acc[i][j]) : "l"(av.y), "l"(bv[j].y));
                }
            }
        }

#pragma unroll
        for (int i = 0; i < 8; i++) {
            float* Tr = g_T + (size_t)(m0 + r0 + i) * ODIM + c0;
#pragma unroll
            for (int j = 0; j < 4; j++) {
                float lo, hi;
                asm("mov.b64 {%0, %1}, %2;" : "=f"(lo), "=f"(hi) : "l"(acc[i][j]));
                Tr[tx + 16 * j] = lo + hi;
            }
        }
    } else {
        // ================= SCAN block: acc_ih = sum_j A_ij*max(ed_j, r_i*eq_j) =
        float4* sed = (float4*)sm;             // exp(dst) [NN]
        float4* seq = (float4*)(sm + NN * 4);  // exp(0.2*dst) [NN]
        const int sid = blockIdx.x >> 1;
        const int b = sid >> 6;
        const int l = tid & 31;
        const int r0 = (sid & 63) * 32 + (tid >> 5) * 4;

        {
            const float4* ge = (const float4*)(g_ed + (size_t)b * NN * 8);
            for (int t = tid; t < NN; t += 256) {
                sed[t] = ge[2 * t];
                seq[t] = ge[2 * t + 1];
            }
        }
        __syncthreads();

        float rr[4][4];
#pragma unroll
        for (int ii = 0; ii < 4; ii++) {
            float4 rv = *(const float4*)&g_r[(size_t)(b * NN + r0 + ii) * 4];
            rr[ii][0] = rv.x; rr[ii][1] = rv.y; rr[ii][2] = rv.z; rr[ii][3] = rv.w;
        }

        const float* Ar[4];
#pragma unroll
        for (int ii = 0; ii < 4; ii++)
            Ar[ii] = A + ((size_t)b * NN + (r0 + ii)) * NN;

        float acc[4][4];
#pragma unroll
        for (int ii = 0; ii < 4; ii++)
#pragma unroll
            for (int h = 0; h < 4; h++) acc[ii][h] = 0.f;

        float cur[4][4], nxt[4][4];
#pragma unroll
        for (int s = 0; s < 4; s++)
#pragma unroll
            for (int ii = 0; ii < 4; ii++)
                cur[s][ii] = __ldcs(&Ar[ii][l + 32 * s]);

        for (int rnd = 0; rnd < 16; rnd++) {
            const int jb = (rnd < 15) ? (rnd + 1) * 128 + l : rnd * 128 + l;
#pragma unroll
            for (int s = 0; s < 4; s++)
#pragma unroll
                for (int ii = 0; ii < 4; ii++)
                    nxt[s][ii] = __ldcs(&Ar[ii][jb + 32 * s]);

#pragma unroll
            for (int s = 0; s < 4; s++) {
                const int j = rnd * 128 + s * 32 + l;
                float4 ed = sed[j];
                float4 eq = seq[j];
#pragma unroll
                for (int ii = 0; ii < 4; ii++) {
                    const float a = cur[s][ii];
                    acc[ii][0] = fmaf(a, fmaxf(ed.x, rr[ii][0] * eq.x), acc[ii][0]);
                    acc[ii][1] = fmaf(a, fmaxf(ed.y, rr[ii][1] * eq.y), acc[ii][1]);
                    acc[ii][2] = fmaf(a, fmaxf(ed.z, rr[ii][2] * eq.z), acc[ii][2]);
                    acc[ii][3] = fmaf(a, fmaxf(ed.w, rr[ii][3] * eq.w), acc[ii][3]);
                }
            }
#pragma unroll
            for (int s = 0; s < 4; s++)
#pragma unroll
                for (int ii = 0; ii < 4; ii++) cur[s][ii] = nxt[s][ii];
        }

#pragma unroll
        for (int off = 16; off; off >>= 1)
#pragma unroll
            for (int ii = 0; ii < 4; ii++)
#pragma unroll
                for (int h = 0; h < 4; h++)
                    acc[ii][h] += __shfl_xor_sync(0xffffffffu, acc[ii][h], off);

        if (l == 0) {
#pragma unroll
            for (int ii = 0; ii < 4; ii++) {
                float* gp = g_acc + (size_t)(b * NN + r0 + ii) * 4;
#pragma unroll
                for (int h = 0; h < 4; h++) gp[h] = acc[ii][h];
            }
        }
    }
}

// ---------------------------------------------------------------------------
// Kernel 4: out = (num/acc) * T   (4 rows per block)
// ---------------------------------------------------------------------------
__global__ __launch_bounds__(256) void scale_kernel(float* __restrict__ out) {
    const int tid = threadIdx.x;
    const int r = tid >> 6;
    const int f = tid & 63;
    const size_t row = (size_t)blockIdx.x * 4 + r;
    const int h = f >> 4;
    float diag = __fdividef(g_num[row * 4 + h], g_acc[row * 4 + h]);
    float4 t = ((const float4*)(g_T + row * ODIM))[f];
    ((float4*)(out + row * ODIM))[f] =
        make_float4(t.x * diag, t.y * diag, t.z * diag, t.w * diag);
}

// ---------------------------------------------------------------------------
extern "C" void kernel_launch(void* const* d_in, const int* in_sizes, int n_in,
                              void* d_out, int out_size) {
    const float* A    = (const float*)d_in[0];
    const float* X    = (const float*)d_in[1];
    const float* W    = (const float*)d_in[2];
    const float* asrc = (const float*)d_in[3];
    const float* adst = (const float*)d_in[4];
    float* out = (float*)d_out;

    cudaFuncSetAttribute(fused_kernel, cudaFuncAttributeMaxDynamicSharedMemorySize,
                         FUSED_SMEM);

    vec_kernel<<<8, 256>>>(W, asrc, adst);
    row_kernel<<<NROWS / 8, 256>>>(X);
    fused_kernel<<<1024, 256, FUSED_SMEM>>>(A, X, W);
    scale_kernel<<<NROWS / 4, 256>>>(out);
}